// round 16
// baseline (speedup 1.0000x reference)
#include <cuda_runtime.h>
#include <cuda_bf16.h>
#include <math.h>
#include <stdint.h>

#define Bb 8
#define Tt 24
#define Nn 768
#define Ee 24576
#define Hh 64
#define BE 196608              // B*E
#define PRED_ELEMS (Bb*Tt*Nn)  // 147456
#define CTA_T 192              // 6 warps, 192 rows/CTA

// ---------------- device scratch (static, no allocs) ----------------
__device__ float g_stat[4];
__device__ float g_hn[Bb*Nn];
__device__ float g_sumhn[Bb];
__device__ int   g_cnt_raw[Nn];
__device__ int   g_rowptr[Nn+1];
__device__ int   g_cursor[Nn];
__device__ int   g_colidx[Ee];
__device__ int   g_cnt[Nn];
__device__ float g_erep[Tt*BE];      // 18.9 MB

// ---------------- SMEM map (f32/u32 units) ----------------
// 0..9215 : B-fragment images (u32), 144 frags x 64 u32 (bf16)
//   Whh (g,nt,kt) = g*32+nt*4+kt  (g=0r,1z,2n) ; W1 = 96+nt*4+kt
//   x-frag R = 128+nt ; x-frag Z = 136+nt
#define GI4_O  9216    // float4 per (g*64+j): {wih_f0, wih_f1, wih_f2, bias}
#define BHN_O  9984    // bhh n-part per j (64)
#define MB2_O  10048   // float2 per j: {b1, W2}
#define EA0_O  10176   // 192 rows
#define EA1_O  10432
#define SMEM_F32 10688
#define SMEM_SZ  (SMEM_F32*4)   // 42752 B

// m16n8k16 bf16 mma (sm_80+ baseline)
#define MMA(D,A,b0,b1) \
  asm("mma.sync.aligned.m16n8k16.row.col.f32.bf16.bf16.f32 " \
      "{%0,%1,%2,%3}, {%4,%5,%6,%7}, {%8,%9}, {%0,%1,%2,%3};" \
      : "+f"((D)[0]),"+f"((D)[1]),"+f"((D)[2]),"+f"((D)[3]) \
      : "r"((A)[0]),"r"((A)[1]),"r"((A)[2]),"r"((A)[3]), "r"(b0),"r"(b1))

#define MMAX(D,a0,a1,b0,b1) \
  asm("mma.sync.aligned.m16n8k16.row.col.f32.bf16.bf16.f32 " \
      "{%0,%1,%2,%3}, {%4,%5,%6,%7}, {%8,%9}, {%0,%1,%2,%3};" \
      : "+f"((D)[0]),"+f"((D)[1]),"+f"((D)[2]),"+f"((D)[3]) \
      : "r"(a0),"r"(a1),"r"(0u),"r"(0u), "r"(b0),"r"(b1))

__device__ __forceinline__ float tanhfast(float x){
  float y; asm("tanh.approx.f32 %0,%1;":"=f"(y):"f"(x)); return y;
}
__device__ __forceinline__ float sigfast(float x){
  return 0.5f*tanhfast(0.5f*x)+0.5f;
}
__device__ __forceinline__ float ubfh(uint32_t v, int hf){
  return __bfloat162float(__ushort_as_bfloat16((unsigned short)(hf?(v>>16):(v&0xffff))));
}
__device__ __forceinline__ uint32_t pk_bf2(float x, float y){  // {lo16=x, hi16=y}
  uint32_t r; asm("cvt.rn.bf16x2.f32 %0, %1, %2;":"=r"(r):"f"(y),"f"(x)); return r;
}
// {lo16=bf16(v), hi16=bf16(v-bf16(v))}
__device__ __forceinline__ uint32_t split2(float v){
  float vh = __bfloat162float(__float2bfloat16(v));
  return pk_bf2(vh, v - vh);
}

// ---------------- prep kernels (proven) ----------------
__global__ void kstat(const float* __restrict__ eattr){
  __shared__ double red[1024];
  int tid = threadIdx.x;
  double s0=0,s1=0,q0=0,q1=0;
  for (int e=tid; e<Ee; e+=1024){
    double a=eattr[2*e], b=eattr[2*e+1];
    s0+=a; s1+=b; q0+=a*a; q1+=b*b;
  }
  double vals[4]={s0,s1,q0,q1};
  double out[4];
  for (int v=0; v<4; ++v){
    red[tid]=vals[v]; __syncthreads();
    for (int off=512; off; off>>=1){ if (tid<off) red[tid]+=red[tid+off]; __syncthreads(); }
    out[v]=red[0]; __syncthreads();
  }
  if (tid==0){
    double m0=out[0]/Ee, m1=out[1]/Ee;
    double v0=(out[2]-out[0]*out[0]/Ee)/(double)(Ee-1);
    double v1=(out[3]-out[1]*out[1]/Ee)/(double)(Ee-1);
    g_stat[0]=(float)m0; g_stat[1]=(float)m1;
    g_stat[2]=(float)(1.0/sqrt(v0)); g_stat[3]=(float)(1.0/sqrt(v1));
  }
  if (tid<Nn) g_cnt_raw[tid]=0;
}

__global__ void kcount(const int* __restrict__ eidx){
  int e = blockIdx.x*256+threadIdx.x;
  if (e<Ee) atomicAdd(&g_cnt_raw[eidx[Ee+e]],1);
}

__global__ void kscan(){
  __shared__ int a[Nn];
  int t=threadIdx.x;
  if (t<Nn) a[t]=g_cnt_raw[t];
  __syncthreads();
  for (int d=1; d<Nn; d<<=1){
    int v=0;
    if (t<Nn && t>=d) v=a[t-d];
    __syncthreads();
    if (t<Nn) a[t]+=v;
    __syncthreads();
  }
  if (t<Nn){ g_rowptr[t+1]=a[t]; g_cursor[t]=a[t]-g_cnt_raw[t]; }
  if (t==0) g_rowptr[0]=0;
}

__global__ void kfill(const int* __restrict__ eidx){
  int e = blockIdx.x*256+threadIdx.x;
  if (e<Ee){ int pos=atomicAdd(&g_cursor[eidx[Ee+e]],1); g_colidx[pos]=e; }
}

__global__ void kfix(const int* __restrict__ eidx){
  int t = blockIdx.x*256+threadIdx.x;
  if (t>=Nn) return;
  int rs=g_rowptr[t], re=g_rowptr[t+1];
  for (int i=rs+1;i<re;i++){
    int key=g_colidx[i]; int j=i-1;
    while(j>=rs && g_colidx[j]>key){ g_colidx[j+1]=g_colidx[j]; j--; }
    g_colidx[j+1]=key;
  }
  int w=rs;
  for (int i=rs;i<re;i++){
    int e=g_colidx[i]; int src=eidx[e];
    bool later=false;
    for (int j2=i+1;j2<re;j2++){ if (eidx[g_colidx[j2]]==src){later=true;break;} }
    if (!later) g_colidx[w++]=e;
  }
  g_cnt[t]=w-rs;
}

__global__ void khn(const float* __restrict__ pm25,
                    const float* __restrict__ Wn, const float* __restrict__ bn){
  __shared__ float red[256];
  int b=blockIdx.x, t=threadIdx.x;
  float w=Wn[0], bb=bn[0];
  float s=0.f;
  for (int n=t;n<Nn;n+=256){ float h=pm25[b*Nn+n]*w+bb; g_hn[b*Nn+n]=h; s+=h; }
  red[t]=s; __syncthreads();
  for(int off=128;off;off>>=1){ if(t<off) red[t]+=red[t+off]; __syncthreads(); }
  if(t==0) g_sumhn[b]=red[0];
}

// ---------------- main GRU+MLP: HMMA bf16, 1 accumulator + packed r/n, 2 CTAs/SM ----------------
__global__ void __launch_bounds__(CTA_T,2) kgru(
    const float* __restrict__ feature, const int* __restrict__ eidx,
    const float* __restrict__ eattr,   const float* __restrict__ wmean,
    const float* __restrict__ wstd,    const float* __restrict__ W_ih,
    const float* __restrict__ W_hh,    const float* __restrict__ b_ih,
    const float* __restrict__ b_hh,    const float* __restrict__ W1,
    const float* __restrict__ b1,      const float* __restrict__ W2,
    const float* __restrict__ b2)
{
  extern __shared__ uint32_t su[];
  float* sf = (float*)su;

  const int tid=threadIdx.x, wid=tid>>5, lane=tid&31;
  const int gq=lane>>2, tig=lane&3;
  const int base=blockIdx.x*CTA_T, bIdx=base/Ee, e0=base%Ee;

  // ---- build B-fragment images (bf16), exact mma register layout ----
  for (int idx=tid; idx<9216; idx+=CTA_T){
    int f=idx>>6, r6=idx&63, ln=r6>>1, reg=r6&1;
    int g2=ln>>2, t2=ln&3;
    uint32_t val;
    if (f<96){
      int kt=f&3, nt=(f>>2)&7, g=f>>5;
      int n = g*64 + nt*8 + g2;
      int k0 = kt*16 + t2*2 + reg*8;
      val = pk_bf2(W_hh[k0*192+n], W_hh[(k0+1)*192+n]);
    } else if (f<128){
      int f2=f-96, kt=f2&3, nt=(f2>>2)&7;
      int n = nt*8+g2;
      int k0 = kt*16 + t2*2 + reg*8;
      val = pk_bf2(W1[k0*64+n], W1[(k0+1)*64+n]);
    } else {
      if (reg==1) val = 0u;
      else {
        int g = (f<136)?0:1;          // R or Z
        int j = (f&7)*8 + g2;
        if (t2<3){ float w = W_ih[t2*192 + g*64 + j]; val = pk_bf2(w,w); }
        else {
          float bs = b_ih[g*64+j] + b_hh[g*64+j];
          float bh_ = __bfloat162float(__float2bfloat16(bs));
          val = pk_bf2(bh_, bs-bh_);
        }
      }
    }
    su[idx]=val;
  }
  // ---- gi coefficient table (gate N) + small tables ----
  {
    int g=tid>>6, j=tid&63;          // tid<192 always
    float bias = b_ih[g*64+j] + (g==2 ? 0.f : b_hh[g*64+j]);
    float4 cf = make_float4(W_ih[g*64+j], W_ih[192+g*64+j], W_ih[384+g*64+j], bias);
    *(float4*)&sf[GI4_O + (g*64+j)*4] = cf;
  }
  if (tid<64){
    sf[BHN_O+tid] = b_hh[128+tid];
    sf[MB2_O+tid*2]   = b1[tid];
    sf[MB2_O+tid*2+1] = W2[tid];
  }
  // per-edge constants (own row = base+tid)
  const int   s_reg = eidx[e0+tid];
  const float dd = eattr[2*(e0+tid)], dr = eattr[2*(e0+tid)+1];
  const float dir_reg = dr, c3d_reg = 3.f/dd;
  sf[EA0_O+tid]=(dd-g_stat[0])*g_stat[2];
  sf[EA1_O+tid]=(dr-g_stat[1])*g_stat[3];
  const float wm0=wmean[0], wm1=wmean[1], ws0=wstd[0], ws1=wstd[1];
  const float b2v=b2[0];
  __syncthreads();

  float ea0v[4], ea1v[4];
  #pragma unroll
  for (int ri=0;ri<4;ri++){
    int row = wid*32 + (ri>>1)*16 + (ri&1)*8 + gq;
    ea0v[ri]=sf[EA0_O+row]; ea1v[ri]=sf[EA1_O+row];
  }

  // constant part of the x A-fragment (tig 0:ea0, 1:ea1, 3:(1,1); tig 2 per-step)
  uint32_t xc[2][2];
  #pragma unroll
  for (int rb=0;rb<2;rb++)
    #pragma unroll
    for (int ch=0;ch<2;ch++){
      int ri=rb*2+ch;
      xc[rb][ch] = (tig==0)? split2(ea0v[ri])
                 : (tig==1)? split2(ea1v[ri])
                 : (tig==3)? 0x3F803F80u : 0u;
    }

  uint32_t Ah[2][4][4];
  #pragma unroll
  for(int rb=0;rb<2;rb++)
    #pragma unroll
    for(int kt=0;kt<4;kt++)
      #pragma unroll
      for(int r=0;r<4;r++) Ah[rb][kt][r]=0u;

  float acc[2][8][4];
  uint32_t rP[2][8][2], nP[2][8][2];   // bf16x2-packed gate values

#define SWEEP(F) do{ \
  _Pragma("unroll") \
  for(int kt=0;kt<4;kt++){ \
    _Pragma("unroll") \
    for(int nt=0;nt<8;nt++){ \
      uint2 bh = *(const uint2*)&su[(((F)+nt*4+kt)<<6) + (lane<<1)]; \
      MMA(acc[0][nt], Ah[0][kt], bh.x, bh.y); \
      MMA(acc[1][nt], Ah[1][kt], bh.x, bh.y); \
    } \
  } \
}while(0)

#define XSWEEP(XF) do{ \
  _Pragma("unroll") \
  for(int nt=0;nt<8;nt++){ \
    uint2 bx = *(const uint2*)&su[(((XF)+nt)<<6) + (lane<<1)]; \
    MMAX(acc[0][nt], xa[0][0], xa[0][1], bx.x, bx.y); \
    MMAX(acc[1][nt], xa[1][0], xa[1][1], bx.x, bx.y); \
  } \
}while(0)

#define ZERO() do{ \
  _Pragma("unroll") for(int rb=0;rb<2;rb++) \
  _Pragma("unroll") for(int nt=0;nt<8;nt++) \
  _Pragma("unroll") for(int c=0;c<4;c++) acc[rb][nt][c]=0.f; \
}while(0)

  const float* fp = feature + ((size_t)(bIdx*25+1)*Nn + s_reg)*4 + 2;

  for (int t=0;t<Tt;t++){
    // edge weight for own row, broadcast within warp
    float2 wv = *(const float2*)fp; fp += Nn*4;
    float speed = wv.x*ws0+wm0;
    float wdir  = wv.y*ws1+wm1;
    float myew = fmaxf(c3d_reg*speed*cosf(dir_reg-wdir), 0.f);
    float ewv[4];
    #pragma unroll
    for (int ri=0;ri<4;ri++)
      ewv[ri] = __shfl_sync(0xffffffffu, myew, (ri>>1)*16 + (ri&1)*8 + gq);
    uint32_t xa[2][2];
    #pragma unroll
    for (int rb=0;rb<2;rb++)
      #pragma unroll
      for (int ch=0;ch<2;ch++)
        xa[rb][ch] = (tig==2)? split2(ewv[rb*2+ch]) : xc[rb][ch];

    // ---- gate R (gi folded) -> pack r ----
    ZERO();
    SWEEP(0);
    XSWEEP(128);
    #pragma unroll
    for(int rb=0;rb<2;rb++)
      #pragma unroll
      for(int nt=0;nt<8;nt++){
        rP[rb][nt][0] = pk_bf2(sigfast(acc[rb][nt][0]), sigfast(acc[rb][nt][1]));
        rP[rb][nt][1] = pk_bf2(sigfast(acc[rb][nt][2]), sigfast(acc[rb][nt][3]));
      }

    // ---- gate N (scalar gi) -> pack n ----
    ZERO();
    SWEEP(64);
    #pragma unroll
    for(int rb=0;rb<2;rb++)
      #pragma unroll
      for(int nt=0;nt<8;nt++){
        float nv[4];
        #pragma unroll
        for(int c=0;c<4;c++){
          int par=c&1, ch=c>>1;
          int j = nt*8 + tig*2 + par;
          int ri = rb*2 + ch;
          float4 cf = *(const float4*)&sf[GI4_O + (128+j)*4];
          float bhn = sf[BHN_O+j];
          float gi = ea0v[ri]*cf.x + ea1v[ri]*cf.y + ewv[ri]*cf.z + cf.w;
          float r = ubfh(rP[rb][nt][c>>1], c&1);
          nv[c] = tanhfast(gi + r*(acc[rb][nt][c]+bhn));
        }
        nP[rb][nt][0] = pk_bf2(nv[0],nv[1]);
        nP[rb][nt][1] = pk_bf2(nv[2],nv[3]);
      }

    // ---- gate Z (gi folded) -> h_new directly into A fragments ----
    ZERO();
    SWEEP(32);
    XSWEEP(136);
    #pragma unroll
    for(int rb=0;rb<2;rb++)
      #pragma unroll
      for(int nt=0;nt<8;nt++){
        float hv[4];
        #pragma unroll
        for(int c=0;c<4;c++){
          float z = sigfast(acc[rb][nt][c]);
          int ridx = (nt&1)*2 + (c>>1);
          float hold = ubfh(Ah[rb][nt>>1][ridx], c&1);
          float n = ubfh(nP[rb][nt][c>>1], c&1);
          hv[c] = n + z*(hold-n);
        }
        acc[rb][nt][0]=hv[0]; acc[rb][nt][1]=hv[1]; acc[rb][nt][2]=hv[2]; acc[rb][nt][3]=hv[3];
      }
    #pragma unroll
    for(int rb=0;rb<2;rb++)
      #pragma unroll
      for(int kt=0;kt<4;kt++){
        Ah[rb][kt][0] = pk_bf2(acc[rb][2*kt][0],  acc[rb][2*kt][1]);
        Ah[rb][kt][1] = pk_bf2(acc[rb][2*kt][2],  acc[rb][2*kt][3]);
        Ah[rb][kt][2] = pk_bf2(acc[rb][2*kt+1][0],acc[rb][2*kt+1][1]);
        Ah[rb][kt][3] = pk_bf2(acc[rb][2*kt+1][2],acc[rb][2*kt+1][3]);
      }

    // ---- MLP ----
    ZERO();
    SWEEP(96);
    float p[4] = {0.f,0.f,0.f,0.f};
    #pragma unroll
    for(int nt=0;nt<8;nt++)
      #pragma unroll
      for(int par=0;par<2;par++){
        int j = nt*8 + tig*2 + par;
        float bb1 = sf[MB2_O+j*2], ww2 = sf[MB2_O+j*2+1];
        #pragma unroll
        for(int ri=0;ri<4;ri++){
          int rb=ri>>1, c=(ri&1)*2+par;
          p[ri] += fmaxf(acc[rb][nt][c]+bb1,0.f)*ww2;
        }
      }
    #pragma unroll
    for(int ri=0;ri<4;ri++){
      p[ri] += __shfl_xor_sync(0xffffffffu,p[ri],1);
      p[ri] += __shfl_xor_sync(0xffffffffu,p[ri],2);
    }
    if (tig==0){
      #pragma unroll
      for(int ri=0;ri<4;ri++){
        int row = wid*32 + (ri>>1)*16 + (ri&1)*8 + gq;
        g_erep[t*BE + base + row] = p[ri]+b2v;
      }
    }
  }
#undef SWEEP
#undef XSWEEP
#undef ZERO
}

// ---------------- softmax rows of R + c_pred (proven) ----------------
__global__ void krow(const int* __restrict__ eidx, float* __restrict__ out)
{
  __shared__ float srow[8][Nn];
  const int wid = threadIdx.x>>5, lane=threadIdx.x&31;
  const int gid = blockIdx.x*8 + wid;
  const int tgt = gid % Nn;
  const int bt  = gid / Nn;
  const int t   = bt % Tt;
  const int b   = bt / Tt;
  const int rs  = g_rowptr[tgt];
  const int cnt = g_cnt[tgt];
  const float* er  = g_erep + (size_t)t*BE + (size_t)b*Ee;
  const float* hnb = g_hn + b*Nn;

  float vmax=0.f;
  for (int i=lane;i<cnt;i+=32){ float v=er[g_colidx[rs+i]]; vmax=fmaxf(vmax,v); }
  #pragma unroll
  for(int off=16;off;off>>=1) vmax=fmaxf(vmax,__shfl_xor_sync(0xffffffffu,vmax,off));

  float se=0.f, shw=0.f, shf=0.f;
  for (int i=lane;i<cnt;i+=32){
    int e=g_colidx[rs+i];
    float v=er[e];
    float ex=__expf(v-vmax);
    float hv=hnb[eidx[e]];
    se+=ex; shw+=ex*hv; shf+=hv;
  }
  #pragma unroll
  for(int off=16;off;off>>=1){
    se +=__shfl_xor_sync(0xffffffffu,se ,off);
    shw+=__shfl_xor_sync(0xffffffffu,shw,off);
    shf+=__shfl_xor_sync(0xffffffffu,shf,off);
  }
  float ez  = __expf(-vmax);
  float inv = __fdividef(1.f, (float)(Nn-cnt)*ez + se);
  float defv= ez*inv;
  if (lane==0) out[gid] = (ez*(g_sumhn[b]-shf)+shw)*inv;

  float* row = srow[wid];
  for (int s=lane;s<Nn;s+=32) row[s]=defv;
  __syncwarp();
  for (int i=lane;i<cnt;i+=32){
    int e=g_colidx[rs+i];
    row[eidx[e]] = __expf(er[e]-vmax)*inv;
  }
  __syncwarp();
  float* dst = out + PRED_ELEMS + (size_t)gid*Nn;
  float4* d4=(float4*)dst; const float4* s4=(const float4*)row;
  for (int s=lane;s<Nn/4;s+=32) d4[s]=s4[s];
}

// ---------------- launch (kgru 4th app launch => ncu slot 6) ----------------
extern "C" void kernel_launch(void* const* d_in, const int* in_sizes, int n_in,
                              void* d_out, int out_size){
  const float* pm25   =(const float*)d_in[0];
  const float* feature=(const float*)d_in[1];
  const int*   eidx   =(const int*)  d_in[2];
  const float* eattr  =(const float*)d_in[3];
  const float* wmean  =(const float*)d_in[4];
  const float* wstd   =(const float*)d_in[5];
  const float* W_ih   =(const float*)d_in[6];
  const float* W_hh   =(const float*)d_in[7];
  const float* b_ih   =(const float*)d_in[8];
  const float* b_hh   =(const float*)d_in[9];
  const float* W1     =(const float*)d_in[10];
  const float* b1     =(const float*)d_in[11];
  const float* W2     =(const float*)d_in[12];
  const float* b2     =(const float*)d_in[13];
  const float* W_node =(const float*)d_in[14];
  const float* b_node =(const float*)d_in[15];
  float* out=(float*)d_out;

  cudaFuncSetAttribute(kgru, cudaFuncAttributeMaxDynamicSharedMemorySize, SMEM_SZ);

  kstat <<<1,1024>>>(eattr);
  kcount<<<96,256>>>(eidx);
  kscan <<<1,1024>>>();
  kgru  <<<1024,CTA_T,SMEM_SZ>>>(feature,eidx,eattr,wmean,wstd,
                                 W_ih,W_hh,b_ih,b_hh,W1,b1,W2,b2);
  kfill <<<96,256>>>(eidx);
  kfix  <<<3,256>>>(eidx);
  khn   <<<8,256>>>(pm25,W_node,b_node);
  krow  <<<18432,256>>>(eidx,out);
}

// round 17
// speedup vs baseline: 1.1029x; 1.1029x over previous
#include <cuda_runtime.h>
#include <cuda_bf16.h>
#include <math.h>
#include <stdint.h>

#define Bb 8
#define Tt 24
#define Nn 768
#define Ee 24576
#define Hh 64
#define BE 196608              // B*E
#define PRED_ELEMS (Bb*Tt*Nn)  // 147456
#define CTA_T 256              // 8 warps, 16 rows/warp = 128 rows/CTA

// ---------------- device scratch (static, no allocs) ----------------
__device__ float g_stat[4];
__device__ float g_hn[Bb*Nn];
__device__ float g_sumhn[Bb];
__device__ int   g_cnt_raw[Nn];
__device__ int   g_rowptr[Nn+1];
__device__ int   g_cursor[Nn];
__device__ int   g_colidx[Ee];
__device__ int   g_cnt[Nn];
__device__ float g_erep[Tt*BE];      // 18.9 MB

// ---------------- SMEM map (f32/u32 units) ----------------
// 0..9215 : B-fragment images (u32), 144 frags x 64 u32 (bf16)
//   Whh (g,nt,kt) = g*32+nt*4+kt  (g=0r,1z,2n) ; W1 = 96+nt*4+kt
//   x-frag R = 128+nt ; x-frag Z = 136+nt
#define GI4_O  9216    // float4 per (g*64+j): {wih_f0, wih_f1, wih_f2, bias}
#define BHN_O  9984    // bhh n-part per j (64)
#define MB2_O  10048   // float2 per j: {b1, W2}
#define EA0_O  10176   // 128 rows
#define EA1_O  10432
#define SMEM_F32 10688
#define SMEM_SZ  (SMEM_F32*4)   // 42752 B

// m16n8k16 bf16 mma (sm_80+ baseline)
#define MMA(D,A,b0,b1) \
  asm("mma.sync.aligned.m16n8k16.row.col.f32.bf16.bf16.f32 " \
      "{%0,%1,%2,%3}, {%4,%5,%6,%7}, {%8,%9}, {%0,%1,%2,%3};" \
      : "+f"((D)[0]),"+f"((D)[1]),"+f"((D)[2]),"+f"((D)[3]) \
      : "r"((A)[0]),"r"((A)[1]),"r"((A)[2]),"r"((A)[3]), "r"(b0),"r"(b1))

#define MMAX(D,a0,a1,b0,b1) \
  asm("mma.sync.aligned.m16n8k16.row.col.f32.bf16.bf16.f32 " \
      "{%0,%1,%2,%3}, {%4,%5,%6,%7}, {%8,%9}, {%0,%1,%2,%3};" \
      : "+f"((D)[0]),"+f"((D)[1]),"+f"((D)[2]),"+f"((D)[3]) \
      : "r"(a0),"r"(a1),"r"(0u),"r"(0u), "r"(b0),"r"(b1))

__device__ __forceinline__ float tanhfast(float x){
  float y; asm("tanh.approx.f32 %0,%1;":"=f"(y):"f"(x)); return y;
}
__device__ __forceinline__ float sigfast(float x){
  return 0.5f*tanhfast(0.5f*x)+0.5f;
}
__device__ __forceinline__ float ubfh(uint32_t v, int hf){
  return __bfloat162float(__ushort_as_bfloat16((unsigned short)(hf?(v>>16):(v&0xffff))));
}
__device__ __forceinline__ uint32_t pk_bf2(float x, float y){  // {lo16=x, hi16=y}
  uint32_t r; asm("cvt.rn.bf16x2.f32 %0, %1, %2;":"=r"(r):"f"(y),"f"(x)); return r;
}
// {lo16=bf16(v), hi16=bf16(v-bf16(v))}
__device__ __forceinline__ uint32_t split2(float v){
  float vh = __bfloat162float(__float2bfloat16(v));
  return pk_bf2(vh, v - vh);
}

// ---------------- prep kernels (proven) ----------------
__global__ void kstat(const float* __restrict__ eattr){
  __shared__ double red[1024];
  int tid = threadIdx.x;
  double s0=0,s1=0,q0=0,q1=0;
  for (int e=tid; e<Ee; e+=1024){
    double a=eattr[2*e], b=eattr[2*e+1];
    s0+=a; s1+=b; q0+=a*a; q1+=b*b;
  }
  double vals[4]={s0,s1,q0,q1};
  double out[4];
  for (int v=0; v<4; ++v){
    red[tid]=vals[v]; __syncthreads();
    for (int off=512; off; off>>=1){ if (tid<off) red[tid]+=red[tid+off]; __syncthreads(); }
    out[v]=red[0]; __syncthreads();
  }
  if (tid==0){
    double m0=out[0]/Ee, m1=out[1]/Ee;
    double v0=(out[2]-out[0]*out[0]/Ee)/(double)(Ee-1);
    double v1=(out[3]-out[1]*out[1]/Ee)/(double)(Ee-1);
    g_stat[0]=(float)m0; g_stat[1]=(float)m1;
    g_stat[2]=(float)(1.0/sqrt(v0)); g_stat[3]=(float)(1.0/sqrt(v1));
  }
  if (tid<Nn) g_cnt_raw[tid]=0;
}

__global__ void kcount(const int* __restrict__ eidx){
  int e = blockIdx.x*256+threadIdx.x;
  if (e<Ee) atomicAdd(&g_cnt_raw[eidx[Ee+e]],1);
}

__global__ void kscan(){
  __shared__ int a[Nn];
  int t=threadIdx.x;
  if (t<Nn) a[t]=g_cnt_raw[t];
  __syncthreads();
  for (int d=1; d<Nn; d<<=1){
    int v=0;
    if (t<Nn && t>=d) v=a[t-d];
    __syncthreads();
    if (t<Nn) a[t]+=v;
    __syncthreads();
  }
  if (t<Nn){ g_rowptr[t+1]=a[t]; g_cursor[t]=a[t]-g_cnt_raw[t]; }
  if (t==0) g_rowptr[0]=0;
}

__global__ void kfill(const int* __restrict__ eidx){
  int e = blockIdx.x*256+threadIdx.x;
  if (e<Ee){ int pos=atomicAdd(&g_cursor[eidx[Ee+e]],1); g_colidx[pos]=e; }
}

__global__ void kfix(const int* __restrict__ eidx){
  int t = blockIdx.x*256+threadIdx.x;
  if (t>=Nn) return;
  int rs=g_rowptr[t], re=g_rowptr[t+1];
  for (int i=rs+1;i<re;i++){
    int key=g_colidx[i]; int j=i-1;
    while(j>=rs && g_colidx[j]>key){ g_colidx[j+1]=g_colidx[j]; j--; }
    g_colidx[j+1]=key;
  }
  int w=rs;
  for (int i=rs;i<re;i++){
    int e=g_colidx[i]; int src=eidx[e];
    bool later=false;
    for (int j2=i+1;j2<re;j2++){ if (eidx[g_colidx[j2]]==src){later=true;break;} }
    if (!later) g_colidx[w++]=e;
  }
  g_cnt[t]=w-rs;
}

__global__ void khn(const float* __restrict__ pm25,
                    const float* __restrict__ Wn, const float* __restrict__ bn){
  __shared__ float red[256];
  int b=blockIdx.x, t=threadIdx.x;
  float w=Wn[0], bb=bn[0];
  float s=0.f;
  for (int n=t;n<Nn;n+=256){ float h=pm25[b*Nn+n]*w+bb; g_hn[b*Nn+n]=h; s+=h; }
  red[t]=s; __syncthreads();
  for(int off=128;off;off>>=1){ if(t<off) red[t]+=red[t+off]; __syncthreads(); }
  if(t==0) g_sumhn[b]=red[0];
}

// ---------------- main GRU+MLP: HMMA bf16, 16 rows/warp, 2 CTAs/SM (16 warps) ----------------
__global__ void __launch_bounds__(CTA_T,2) kgru(
    const float* __restrict__ feature, const int* __restrict__ eidx,
    const float* __restrict__ eattr,   const float* __restrict__ wmean,
    const float* __restrict__ wstd,    const float* __restrict__ W_ih,
    const float* __restrict__ W_hh,    const float* __restrict__ b_ih,
    const float* __restrict__ b_hh,    const float* __restrict__ W1,
    const float* __restrict__ b1,      const float* __restrict__ W2,
    const float* __restrict__ b2)
{
  extern __shared__ uint32_t su[];
  float* sf = (float*)su;

  const int tid=threadIdx.x, wid=tid>>5, lane=tid&31;
  const int gq=lane>>2, tig=lane&3;
  const int base=blockIdx.x*128, bIdx=base/Ee, e0=base%Ee;   // 128 rows/CTA

  // ---- build B-fragment images (bf16), exact mma register layout ----
  for (int idx=tid; idx<9216; idx+=CTA_T){
    int f=idx>>6, r6=idx&63, ln=r6>>1, reg=r6&1;
    int g2=ln>>2, t2=ln&3;
    uint32_t val;
    if (f<96){
      int kt=f&3, nt=(f>>2)&7, g=f>>5;
      int n = g*64 + nt*8 + g2;
      int k0 = kt*16 + t2*2 + reg*8;
      val = pk_bf2(W_hh[k0*192+n], W_hh[(k0+1)*192+n]);
    } else if (f<128){
      int f2=f-96, kt=f2&3, nt=(f2>>2)&7;
      int n = nt*8+g2;
      int k0 = kt*16 + t2*2 + reg*8;
      val = pk_bf2(W1[k0*64+n], W1[(k0+1)*64+n]);
    } else {
      if (reg==1) val = 0u;
      else {
        int g = (f<136)?0:1;          // R or Z
        int j = (f&7)*8 + g2;
        if (t2<3){ float w = W_ih[t2*192 + g*64 + j]; val = pk_bf2(w,w); }
        else {
          float bs = b_ih[g*64+j] + b_hh[g*64+j];
          float bh_ = __bfloat162float(__float2bfloat16(bs));
          val = pk_bf2(bh_, bs-bh_);
        }
      }
    }
    su[idx]=val;
  }
  // ---- gi coefficient table (gate N) + small tables ----
  if (tid<192){
    int g=tid>>6, j=tid&63;
    float bias = b_ih[g*64+j] + (g==2 ? 0.f : b_hh[g*64+j]);
    float4 cf = make_float4(W_ih[g*64+j], W_ih[192+g*64+j], W_ih[384+g*64+j], bias);
    *(float4*)&sf[GI4_O + (g*64+j)*4] = cf;
  }
  if (tid<64){
    sf[BHN_O+tid] = b_hh[128+tid];
    sf[MB2_O+tid*2]   = b1[tid];
    sf[MB2_O+tid*2+1] = W2[tid];
  }
  if (tid<128){
    int e=e0+tid;
    float dd=eattr[2*e], dr=eattr[2*e+1];
    sf[EA0_O+tid]=(dd-g_stat[0])*g_stat[2];
    sf[EA1_O+tid]=(dr-g_stat[1])*g_stat[3];
  }
  // per-edge constants for ew (own row = e0 + wid*16 + (lane&15))
  const int   eown = e0 + wid*16 + (lane&15);
  const int   s_reg = eidx[eown];
  const float dd_o = eattr[2*eown], dr_o = eattr[2*eown+1];
  const float dir_reg = dr_o, c3d_reg = 3.f/dd_o;
  const float wm0=wmean[0], wm1=wmean[1], ws0=wstd[0], ws1=wstd[1];
  const float b2v=b2[0];
  __syncthreads();

  float ea0v[2], ea1v[2];
  #pragma unroll
  for (int ch=0;ch<2;ch++){
    int row = wid*16 + ch*8 + gq;
    ea0v[ch]=sf[EA0_O+row]; ea1v[ch]=sf[EA1_O+row];
  }

  // constant part of the x A-fragment (tig 0:ea0, 1:ea1, 3:(1,1); tig 2 per-step)
  uint32_t xc[2];
  #pragma unroll
  for (int ch=0;ch<2;ch++){
    xc[ch] = (tig==0)? split2(ea0v[ch])
           : (tig==1)? split2(ea1v[ch])
           : (tig==3)? 0x3F803F80u : 0u;
  }

  uint32_t Ah[4][4];
  #pragma unroll
  for(int kt=0;kt<4;kt++)
    #pragma unroll
    for(int r=0;r<4;r++) Ah[kt][r]=0u;

  float accA[8][4], accB[8][4];

#define SWEEP(ACC,F) do{ \
  _Pragma("unroll") \
  for(int kt=0;kt<4;kt++){ \
    _Pragma("unroll") \
    for(int nt=0;nt<8;nt++){ \
      uint2 bh = *(const uint2*)&su[(((F)+nt*4+kt)<<6) + (lane<<1)]; \
      MMA(ACC[nt], Ah[kt], bh.x, bh.y); \
    } \
  } \
}while(0)

#define XSWEEP(ACC,XF) do{ \
  _Pragma("unroll") \
  for(int nt=0;nt<8;nt++){ \
    uint2 bx = *(const uint2*)&su[(((XF)+nt)<<6) + (lane<<1)]; \
    MMAX(ACC[nt], xa[0], xa[1], bx.x, bx.y); \
  } \
}while(0)

#define ZERO(ACC) do{ \
  _Pragma("unroll") for(int nt=0;nt<8;nt++) \
  _Pragma("unroll") for(int c=0;c<4;c++) (ACC)[nt][c]=0.f; \
}while(0)

  const float* fp = feature + ((size_t)(bIdx*25+1)*Nn + s_reg)*4 + 2;

  for (int t=0;t<Tt;t++){
    // edge weight for own row, quad-broadcast within warp (no block sync)
    float2 wv = *(const float2*)fp; fp += Nn*4;
    float speed = wv.x*ws0+wm0;
    float wdir  = wv.y*ws1+wm1;
    float myew = fmaxf(c3d_reg*speed*cosf(dir_reg-wdir), 0.f);
    float ewv[2];
    #pragma unroll
    for (int ch=0;ch<2;ch++)
      ewv[ch] = __shfl_sync(0xffffffffu, myew, ch*8 + gq);
    uint32_t xa[2];
    #pragma unroll
    for (int ch=0;ch<2;ch++)
      xa[ch] = (tig==2)? split2(ewv[ch]) : xc[ch];

    // ---- gate R (gi folded) -> accA becomes r ----
    ZERO(accA);
    SWEEP(accA, 0);
    XSWEEP(accA, 128);
    #pragma unroll
    for(int nt=0;nt<8;nt++)
      #pragma unroll
      for(int c=0;c<4;c++)
        accA[nt][c] = sigfast(accA[nt][c]);

    // ---- gate N (scalar gi) -> accB becomes n ----
    ZERO(accB);
    SWEEP(accB, 64);
    #pragma unroll
    for(int nt=0;nt<8;nt++)
      #pragma unroll
      for(int par=0;par<2;par++){
        int j = nt*8 + tig*2 + par;
        float4 cf = *(const float4*)&sf[GI4_O + (128+j)*4];
        float bhn = sf[BHN_O+j];
        #pragma unroll
        for(int ch=0;ch<2;ch++){
          int c = ch*2+par;
          float gi = ea0v[ch]*cf.x + ea1v[ch]*cf.y + ewv[ch]*cf.z + cf.w;
          float pre = gi + accA[nt][c]*(accB[nt][c]+bhn);
          accB[nt][c] = tanhfast(pre);
        }
      }

    // ---- gate Z (gi folded) -> accA; h_new into accA ----
    ZERO(accA);
    SWEEP(accA, 32);
    XSWEEP(accA, 136);
    #pragma unroll
    for(int nt=0;nt<8;nt++)
      #pragma unroll
      for(int c=0;c<4;c++){
        float z = sigfast(accA[nt][c]);
        int ridx = (nt&1)*2 + (c>>1);
        float hold = ubfh(Ah[nt>>1][ridx], c&1);
        float n = accB[nt][c];
        accA[nt][c] = n + z*(hold-n);
      }

    // ---- pack h_new -> A fragments (plain bf16) ----
    #pragma unroll
    for(int kt=0;kt<4;kt++){
      Ah[kt][0] = pk_bf2(accA[2*kt][0],  accA[2*kt][1]);
      Ah[kt][1] = pk_bf2(accA[2*kt][2],  accA[2*kt][3]);
      Ah[kt][2] = pk_bf2(accA[2*kt+1][0],accA[2*kt+1][1]);
      Ah[kt][3] = pk_bf2(accA[2*kt+1][2],accA[2*kt+1][3]);
    }

    // ---- MLP: accB = h_new @ W1 ----
    ZERO(accB);
    SWEEP(accB, 96);
    float p[2] = {0.f,0.f};
    #pragma unroll
    for(int nt=0;nt<8;nt++)
      #pragma unroll
      for(int par=0;par<2;par++){
        int j = nt*8 + tig*2 + par;
        float bb1 = sf[MB2_O+j*2], ww2 = sf[MB2_O+j*2+1];
        #pragma unroll
        for(int ch=0;ch<2;ch++)
          p[ch] += fmaxf(accB[nt][ch*2+par]+bb1,0.f)*ww2;
      }
    #pragma unroll
    for(int ch=0;ch<2;ch++){
      p[ch] += __shfl_xor_sync(0xffffffffu,p[ch],1);
      p[ch] += __shfl_xor_sync(0xffffffffu,p[ch],2);
    }
    if (tig==0){
      #pragma unroll
      for(int ch=0;ch<2;ch++){
        int row = wid*16 + ch*8 + gq;
        g_erep[t*BE + base + row] = p[ch]+b2v;
      }
    }
  }
#undef SWEEP
#undef XSWEEP
#undef ZERO
}

// ---------------- softmax rows of R + c_pred (proven) ----------------
__global__ void krow(const int* __restrict__ eidx, float* __restrict__ out)
{
  __shared__ float srow[8][Nn];
  const int wid = threadIdx.x>>5, lane=threadIdx.x&31;
  const int gid = blockIdx.x*8 + wid;
  const int tgt = gid % Nn;
  const int bt  = gid / Nn;
  const int t   = bt % Tt;
  const int b   = bt / Tt;
  const int rs  = g_rowptr[tgt];
  const int cnt = g_cnt[tgt];
  const float* er  = g_erep + (size_t)t*BE + (size_t)b*Ee;
  const float* hnb = g_hn + b*Nn;

  float vmax=0.f;
  for (int i=lane;i<cnt;i+=32){ float v=er[g_colidx[rs+i]]; vmax=fmaxf(vmax,v); }
  #pragma unroll
  for(int off=16;off;off>>=1) vmax=fmaxf(vmax,__shfl_xor_sync(0xffffffffu,vmax,off));

  float se=0.f, shw=0.f, shf=0.f;
  for (int i=lane;i<cnt;i+=32){
    int e=g_colidx[rs+i];
    float v=er[e];
    float ex=__expf(v-vmax);
    float hv=hnb[eidx[e]];
    se+=ex; shw+=ex*hv; shf+=hv;
  }
  #pragma unroll
  for(int off=16;off;off>>=1){
    se +=__shfl_xor_sync(0xffffffffu,se ,off);
    shw+=__shfl_xor_sync(0xffffffffu,shw,off);
    shf+=__shfl_xor_sync(0xffffffffu,shf,off);
  }
  float ez  = __expf(-vmax);
  float inv = __fdividef(1.f, (float)(Nn-cnt)*ez + se);
  float defv= ez*inv;
  if (lane==0) out[gid] = (ez*(g_sumhn[b]-shf)+shw)*inv;

  float* row = srow[wid];
  for (int s=lane;s<Nn;s+=32) row[s]=defv;
  __syncwarp();
  for (int i=lane;i<cnt;i+=32){
    int e=g_colidx[rs+i];
    row[eidx[e]] = __expf(er[e]-vmax)*inv;
  }
  __syncwarp();
  float* dst = out + PRED_ELEMS + (size_t)gid*Nn;
  float4* d4=(float4*)dst; const float4* s4=(const float4*)row;
  for (int s=lane;s<Nn/4;s+=32) d4[s]=s4[s];
}

// ---------------- launch (kgru 4th app launch => ncu slot 6) ----------------
extern "C" void kernel_launch(void* const* d_in, const int* in_sizes, int n_in,
                              void* d_out, int out_size){
  const float* pm25   =(const float*)d_in[0];
  const float* feature=(const float*)d_in[1];
  const int*   eidx   =(const int*)  d_in[2];
  const float* eattr  =(const float*)d_in[3];
  const float* wmean  =(const float*)d_in[4];
  const float* wstd   =(const float*)d_in[5];
  const float* W_ih   =(const float*)d_in[6];
  const float* W_hh   =(const float*)d_in[7];
  const float* b_ih   =(const float*)d_in[8];
  const float* b_hh   =(const float*)d_in[9];
  const float* W1     =(const float*)d_in[10];
  const float* b1     =(const float*)d_in[11];
  const float* W2     =(const float*)d_in[12];
  const float* b2     =(const float*)d_in[13];
  const float* W_node =(const float*)d_in[14];
  const float* b_node =(const float*)d_in[15];
  float* out=(float*)d_out;

  cudaFuncSetAttribute(kgru, cudaFuncAttributeMaxDynamicSharedMemorySize, SMEM_SZ);

  kstat <<<1,1024>>>(eattr);
  kcount<<<96,256>>>(eidx);
  kscan <<<1,1024>>>();
  kgru  <<<1536,CTA_T,SMEM_SZ>>>(feature,eidx,eattr,wmean,wstd,
                                 W_ih,W_hh,b_ih,b_hh,W1,b1,W2,b2);
  kfill <<<96,256>>>(eidx);
  kfix  <<<3,256>>>(eidx);
  khn   <<<8,256>>>(pm25,W_node,b_node);
  krow  <<<18432,256>>>(eidx,out);
}